// round 4
// baseline (speedup 1.0000x reference)
#include <cuda_runtime.h>
#include <math.h>

// ---------------------------------------------------------------------------
// Problem constants (match reference)
// ---------------------------------------------------------------------------
namespace {
constexpr int B  = 2;
constexpr int S  = 2048;
constexpr int D  = 256;
constexpr int H  = 4;
constexpr int HD = 64;
constexpr int L  = 4;
constexpr int V  = 50257;
constexpr int DF = 1024;          // 4*D
constexpr int BS = B * S;         // 4096 tokens
}

// ---------------------------------------------------------------------------
// Scratch (static device globals -- no allocations allowed)
// ---------------------------------------------------------------------------
__device__ float g_h [BS * D];
__device__ float g_n [BS * D];
__device__ float g_q [BS * D];
__device__ float g_k [BS * D];
__device__ float g_v [BS * D];
__device__ float g_o [BS * D];
__device__ float g_f1[BS * DF];
__device__ float g_att[(long long)B * H * S * S];   // 134 MB

#define DEV_INLINE __device__ __forceinline__

DEV_INLINE float gelu_exact(float x) {
    return 0.5f * x * (1.0f + erff(x * 0.70710678118654752f));
}

// ---------------------------------------------------------------------------
// Generic register-tiled SGEMM
//   C[m][n] = alpha * sum_k A[m][k] * B[k][n]   (+bias, +resid, gelu)
//   TRANSB: B stored N-major (B[k][n] = Bp[n*ldb + k])
//   EPI: 0 = bias(optional)   1 = gelu(acc+bias)   2 = resid + acc + bias
//   causal: 0 none; 1 skip blocks fully above diagonal (scores);
//           2 limit K to m0+BM (attn @ V -- masked attn entries are exact 0)
//   Two-level z batching: z -> (z/zdiv, z%zdiv) with separate strides
// ---------------------------------------------------------------------------
template<int BM, int BN, int BK, int TM, int TN, bool TRANSB, int EPI>
__global__ void __launch_bounds__((BM/TM)*(BN/TN))
gemm_k(const float* __restrict__ A,  int lda,
       const float* __restrict__ Bp, int ldb,
       float* __restrict__ C,        int ldc,
       const float* __restrict__ bias,
       const float* __restrict__ R,
       int M, int N, int K, float alpha, int causal,
       int zdiv,
       long long sA1, long long sA2,
       long long sB1, long long sB2,
       long long sC1, long long sC2)
{
    constexpr int TX = BN / TN;
    constexpr int TY = BM / TM;
    constexpr int NT = TX * TY;

    const int tid = threadIdx.x;
    const int tx  = tid % TX;
    const int ty  = tid / TX;
    const int n0  = blockIdx.x * BN;
    const int m0  = blockIdx.y * BM;

    if (causal == 1 && n0 > m0 + BM - 1) return;   // fully-masked score block

    {
        const int z  = blockIdx.z;
        const int zb = z / zdiv, zh = z % zdiv;
        A  += zb * sA1 + zh * sA2;
        Bp += zb * sB1 + zh * sB2;
        C  += zb * sC1 + zh * sC2;
        if (EPI == 2) R += zb * sC1 + zh * sC2;
    }

    const int Keff = (causal == 2) ? min(K, m0 + BM) : K;

    __shared__ float As[BK][BM];
    __shared__ float Bs[BK][BN];

    float acc[TM][TN];
    #pragma unroll
    for (int i = 0; i < TM; i++)
        #pragma unroll
        for (int j = 0; j < TN; j++) acc[i][j] = 0.f;

    for (int k0 = 0; k0 < Keff; k0 += BK) {
        // ---- A tile (BM x BK), stored transposed As[k][m] ----
        for (int t = tid; t < BM * (BK / 4); t += NT) {
            int m  = t / (BK / 4);
            int kq = (t % (BK / 4)) * 4;
            float4 v = make_float4(0.f, 0.f, 0.f, 0.f);
            if (m0 + m < M)
                v = *reinterpret_cast<const float4*>(&A[(long long)(m0 + m) * lda + k0 + kq]);
            As[kq + 0][m] = v.x; As[kq + 1][m] = v.y;
            As[kq + 2][m] = v.z; As[kq + 3][m] = v.w;
        }
        // ---- B tile (BK x BN) ----
        if (!TRANSB) {
            for (int t = tid; t < BK * (BN / 4); t += NT) {
                int kk = t / (BN / 4);
                int nq = (t % (BN / 4)) * 4;
                int n  = n0 + nq;
                float4 v = make_float4(0.f, 0.f, 0.f, 0.f);
                if (n + 3 < N) {
                    v = *reinterpret_cast<const float4*>(&Bp[(long long)(k0 + kk) * ldb + n]);
                } else {
                    if (n + 0 < N) v.x = Bp[(long long)(k0 + kk) * ldb + n + 0];
                    if (n + 1 < N) v.y = Bp[(long long)(k0 + kk) * ldb + n + 1];
                    if (n + 2 < N) v.z = Bp[(long long)(k0 + kk) * ldb + n + 2];
                }
                *reinterpret_cast<float4*>(&Bs[kk][nq]) = v;
            }
        } else {
            for (int t = tid; t < BN * (BK / 4); t += NT) {
                int n  = t / (BK / 4);
                int kq = (t % (BK / 4)) * 4;
                float4 v = make_float4(0.f, 0.f, 0.f, 0.f);
                if (n0 + n < N)
                    v = *reinterpret_cast<const float4*>(&Bp[(long long)(n0 + n) * ldb + k0 + kq]);
                Bs[kq + 0][n] = v.x; Bs[kq + 1][n] = v.y;
                Bs[kq + 2][n] = v.z; Bs[kq + 3][n] = v.w;
            }
        }
        __syncthreads();

        #pragma unroll
        for (int kk = 0; kk < BK; kk++) {
            float a[TM], b[TN];
            #pragma unroll
            for (int i = 0; i < TM; i += 4)
                *reinterpret_cast<float4*>(&a[i]) =
                    *reinterpret_cast<const float4*>(&As[kk][ty * TM + i]);
            #pragma unroll
            for (int j = 0; j < TN; j += 4)
                *reinterpret_cast<float4*>(&b[j]) =
                    *reinterpret_cast<const float4*>(&Bs[kk][tx * TN + j]);
            #pragma unroll
            for (int i = 0; i < TM; i++)
                #pragma unroll
                for (int j = 0; j < TN; j++)
                    acc[i][j] = fmaf(a[i], b[j], acc[i][j]);
        }
        __syncthreads();
    }

    // ---- epilogue ----
    #pragma unroll
    for (int i = 0; i < TM; i++) {
        const int m = m0 + ty * TM + i;
        if (m >= M) continue;
        #pragma unroll
        for (int j = 0; j < TN; j++) {
            const int n = n0 + tx * TN + j;
            if (n >= N) continue;
            float v = acc[i][j] * alpha;
            if (bias) v += bias[n];
            if (EPI == 1) v = gelu_exact(v);
            if (EPI == 2) v += R[(long long)m * ldc + n];
            C[(long long)m * ldc + n] = v;
        }
    }
}

// ---------------------------------------------------------------------------
// Embedding: h[b,s,:] = tok_emb[id] + pos_emb[s]
// ---------------------------------------------------------------------------
__global__ void embed_k(const int* __restrict__ ids, const float* __restrict__ tok,
                        const float* __restrict__ pos, float* __restrict__ h)
{
    int idx = blockIdx.x * 256 + threadIdx.x;
    if (idx >= BS * D) return;
    int d  = idx & (D - 1);
    int bs = idx >> 8;              // D == 256
    int s  = bs & (S - 1);
    h[idx] = tok[(long long)ids[bs] * D + d] + pos[s * D + d];
}

// ---------------------------------------------------------------------------
// LayerNorm: one block per row, D=256 threads, eps=1e-5, biased variance
// ---------------------------------------------------------------------------
__global__ void layernorm_k(const float* __restrict__ x, float* __restrict__ y,
                            const float* __restrict__ sc, const float* __restrict__ bi)
{
    const int row = blockIdx.x;
    const int tid = threadIdx.x;        // blockDim = D = 256
    const float v = x[(long long)row * D + tid];

    float s1 = v, s2 = v * v;
    #pragma unroll
    for (int o = 16; o > 0; o >>= 1) {
        s1 += __shfl_xor_sync(0xffffffffu, s1, o);
        s2 += __shfl_xor_sync(0xffffffffu, s2, o);
    }
    __shared__ float a1[8], a2[8];
    if ((tid & 31) == 0) { a1[tid >> 5] = s1; a2[tid >> 5] = s2; }
    __syncthreads();
    if (tid < 32) {
        float t1 = (tid < 8) ? a1[tid] : 0.f;
        float t2 = (tid < 8) ? a2[tid] : 0.f;
        #pragma unroll
        for (int o = 4; o > 0; o >>= 1) {
            t1 += __shfl_xor_sync(0xffffffffu, t1, o);
            t2 += __shfl_xor_sync(0xffffffffu, t2, o);
        }
        if (tid == 0) { a1[0] = t1; a2[0] = t2; }
    }
    __syncthreads();
    const float mean = a1[0] * (1.f / D);
    const float var  = a2[0] * (1.f / D) - mean * mean;
    const float r    = rsqrtf(var + 1e-5f);
    y[(long long)row * D + tid] = (v - mean) * r * sc[tid] + bi[tid];
}

// ---------------------------------------------------------------------------
// Causal softmax over score rows. blockIdx.x = (b*H+h)*S + q; writes exact 0
// for masked positions so the attn@V GEMM can K-limit safely.
// ---------------------------------------------------------------------------
__global__ void softmax_causal_k(float* __restrict__ att)
{
    const int  row   = blockIdx.x;
    const int  q     = row & (S - 1);
    const int  valid = q + 1;
    const int  tid   = threadIdx.x;     // 256
    float* p = att + (long long)row * S;

    float x[S / 256];
    int   cnt = 0;
    float mx  = -INFINITY;
    for (int c = tid; c < valid; c += 256) { x[cnt] = p[c]; mx = fmaxf(mx, x[cnt]); cnt++; }

    __shared__ float sh[8];
    #pragma unroll
    for (int o = 16; o > 0; o >>= 1) mx = fmaxf(mx, __shfl_xor_sync(0xffffffffu, mx, o));
    if ((tid & 31) == 0) sh[tid >> 5] = mx;
    __syncthreads();
    if (tid < 32) {
        float t = (tid < 8) ? sh[tid] : -INFINITY;
        #pragma unroll
        for (int o = 4; o > 0; o >>= 1) t = fmaxf(t, __shfl_xor_sync(0xffffffffu, t, o));
        if (tid == 0) sh[0] = t;
    }
    __syncthreads();
    mx = sh[0];
    __syncthreads();

    float sum = 0.f;
    for (int i = 0; i < cnt; i++) { x[i] = expf(x[i] - mx); sum += x[i]; }
    #pragma unroll
    for (int o = 16; o > 0; o >>= 1) sum += __shfl_xor_sync(0xffffffffu, sum, o);
    if ((tid & 31) == 0) sh[tid >> 5] = sum;
    __syncthreads();
    if (tid < 32) {
        float t = (tid < 8) ? sh[tid] : 0.f;
        #pragma unroll
        for (int o = 4; o > 0; o >>= 1) t += __shfl_xor_sync(0xffffffffu, t, o);
        if (tid == 0) sh[0] = t;
    }
    __syncthreads();
    const float inv = 1.0f / sh[0];

    cnt = 0;
    for (int c = tid; c < valid; c += 256) p[c] = x[cnt++] * inv;
    for (int c = tid; c < S; c += 256) if (c >= valid) p[c] = 0.f;
}

// ---------------------------------------------------------------------------
// Driver -- all launches on the default stream; graph-capturable, no allocs.
// ---------------------------------------------------------------------------
extern "C" void kernel_launch(void* const* d_in, const int* in_sizes, int n_in,
                              void* d_out, int out_size)
{
    (void)in_sizes; (void)n_in; (void)out_size;

    const int*   ids  = (const int*)  d_in[0];
    const float* tok  = (const float*)d_in[1];
    const float* pos  = (const float*)d_in[2];
    const float* Wq   = (const float*)d_in[3];
    const float* bq   = (const float*)d_in[4];
    const float* Wk   = (const float*)d_in[5];
    const float* bk   = (const float*)d_in[6];
    const float* Wv   = (const float*)d_in[7];
    const float* bv   = (const float*)d_in[8];
    const float* Wo   = (const float*)d_in[9];
    const float* bo   = (const float*)d_in[10];
    const float* ln1s = (const float*)d_in[11];
    const float* ln1b = (const float*)d_in[12];
    const float* ln2s = (const float*)d_in[13];
    const float* ln2b = (const float*)d_in[14];
    const float* W1   = (const float*)d_in[15];
    const float* b1   = (const float*)d_in[16];
    const float* W2   = (const float*)d_in[17];
    const float* b2   = (const float*)d_in[18];
    const float* lnfs = (const float*)d_in[19];
    const float* lnfb = (const float*)d_in[20];
    float* out = (float*)d_out;

    float *gh, *gn, *gq, *gk, *gv, *go, *gf, *ga;
    cudaGetSymbolAddress((void**)&gh, g_h);
    cudaGetSymbolAddress((void**)&gn, g_n);
    cudaGetSymbolAddress((void**)&gq, g_q);
    cudaGetSymbolAddress((void**)&gk, g_k);
    cudaGetSymbolAddress((void**)&gv, g_v);
    cudaGetSymbolAddress((void**)&go, g_o);
    cudaGetSymbolAddress((void**)&gf, g_f1);
    cudaGetSymbolAddress((void**)&ga, g_att);

    const long long SD  = (long long)S * D;
    const long long SS  = (long long)S * S;
    const long long HSS = (long long)H * S * S;

    embed_k<<<(BS * D + 255) / 256, 256>>>(ids, tok, pos, gh);

    for (int l = 0; l < L; l++) {
        const float* wq = Wq + (long long)l * D * D;
        const float* wk = Wk + (long long)l * D * D;
        const float* wv = Wv + (long long)l * D * D;
        const float* wo = Wo + (long long)l * D * D;
        const float* w1 = W1 + (long long)l * D * DF;
        const float* w2 = W2 + (long long)l * DF * D;

        // LN1
        layernorm_k<<<BS, D>>>(gh, gn, ln1s + l * D, ln1b + l * D);

        // Q, K, V projections: (4096 x 256) @ (256 x 256) + bias
        dim3 gP(D / 64, BS / 128, 1);
        gemm_k<128,64,8,8,4,false,0><<<gP, 256>>>(gn, D, wq, D, gq, D, bq + l * D, nullptr,
            BS, D, D, 1.f, 0, 1, 0,0,0,0,0,0);
        gemm_k<128,64,8,8,4,false,0><<<gP, 256>>>(gn, D, wk, D, gk, D, bk + l * D, nullptr,
            BS, D, D, 1.f, 0, 1, 0,0,0,0,0,0);
        gemm_k<128,64,8,8,4,false,0><<<gP, 256>>>(gn, D, wv, D, gv, D, bv + l * D, nullptr,
            BS, D, D, 1.f, 0, 1, 0,0,0,0,0,0);

        // Scores = scale * Q @ K^T  (batched over b,h; causal block-skip)
        dim3 gS(S / 128, S / 128, B * H);
        gemm_k<128,128,8,8,8,true,0><<<gS, 256>>>(gq, D, gk, D, ga, S, nullptr, nullptr,
            S, S, HD, 0.125f /* HD^-0.5 */, 1,
            H, SD, HD, SD, HD, HSS, SS);

        // Causal softmax (writes exact zeros for masked cols)
        softmax_causal_k<<<B * H * S, 256>>>(ga);

        // O = attn @ V  (batched; K limited to causal extent per block-row)
        dim3 gA(HD / 64, S / 64, B * H);
        gemm_k<64,64,8,4,4,false,0><<<gA, 256>>>(ga, S, gv, D, go, D, nullptr, nullptr,
            S, HD, S, 1.f, 2,
            H, HSS, SS, SD, HD, SD, HD);

        // h = h + O @ Wo + bo
        gemm_k<128,64,8,8,4,false,2><<<gP, 256>>>(go, D, wo, D, gh, D, bo + l * D, gh,
            BS, D, D, 1.f, 0, 1, 0,0,0,0,0,0);

        // LN2
        layernorm_k<<<BS, D>>>(gh, gn, ln2s + l * D, ln2b + l * D);

        // FFN1: gelu(n @ W1 + b1)   (4096 x 1024)
        dim3 gF1(DF / 128, BS / 128, 1);
        gemm_k<128,128,8,8,8,false,1><<<gF1, 256>>>(gn, D, w1, DF, gf, DF, b1 + l * DF, nullptr,
            BS, DF, D, 1.f, 0, 1, 0,0,0,0,0,0);

        // h = h + f @ W2 + b2
        dim3 gF2(D / 64, BS / 128, 1);
        gemm_k<128,64,8,8,4,false,2><<<gF2, 256>>>(gf, DF, w2, D, gh, D, b2 + l * D, gh,
            BS, D, DF, 1.f, 0, 1, 0,0,0,0,0,0);
    }

    // Final LN
    layernorm_k<<<BS, D>>>(gh, gn, lnfs, lnfb);

    // LM head: logits = n @ tok_emb^T   (4096 x 50257 x 256, NT)
    dim3 gL((V + 127) / 128, BS / 128, 1);
    gemm_k<128,128,8,8,8,true,0><<<gL, 256>>>(gn, D, tok, D, out, V, nullptr, nullptr,
        BS, V, D, 1.f, 0, 1, 0,0,0,0,0,0);
}

// round 8
// speedup vs baseline: 1.2187x; 1.2187x over previous
#include <cuda_runtime.h>
#include <math.h>
#include <stdint.h>

// ---------------------------------------------------------------------------
// Problem constants (match reference)
// ---------------------------------------------------------------------------
namespace {
constexpr int B  = 2;
constexpr int S  = 2048;
constexpr int D  = 256;
constexpr int H  = 4;
constexpr int HD = 64;
constexpr int L  = 4;
constexpr int V  = 50257;
constexpr int DF = 1024;          // 4*D
constexpr int BS = B * S;         // 4096 tokens
}

// ---------------------------------------------------------------------------
// Scratch (static device globals -- no allocations allowed)
// ---------------------------------------------------------------------------
__device__ float g_h [BS * D];
__device__ float g_n [BS * D];
__device__ float g_q [BS * D];
__device__ float g_k [BS * D];
__device__ float g_v [BS * D];
__device__ float g_o [BS * D];
__device__ float g_f1[BS * DF];
__device__ float g_att[(long long)B * H * S * S];   // 134 MB

#define DEV_INLINE __device__ __forceinline__

DEV_INLINE float gelu_exact(float x) {
    return 0.5f * x * (1.0f + erff(x * 0.70710678118654752f));
}

DEV_INLINE float f2tf32(float x) {   // round-to-nearest tf32, kept in fp32 bits
    uint32_t u;
    asm("cvt.rna.tf32.f32 %0, %1;" : "=r"(u) : "f"(x));
    return __uint_as_float(u);
}

// ---------------------------------------------------------------------------
// Generic register-tiled fp32 SGEMM (unchanged math from R3)
//   EPI: 0 = bias(optional)   1 = gelu(acc+bias)   2 = resid + acc + bias
//   causal: 0 none; 1 skip blocks fully above diagonal; 2 K-limit to m0+BM
// ---------------------------------------------------------------------------
template<int BM, int BN, int BK, int TM, int TN, bool TRANSB, int EPI>
__global__ void __launch_bounds__((BM/TM)*(BN/TN))
gemm_k(const float* __restrict__ A,  int lda,
       const float* __restrict__ Bp, int ldb,
       float* __restrict__ C,        int ldc,
       const float* __restrict__ bias,
       const float* __restrict__ R,
       int M, int N, int K, float alpha, int causal,
       int zdiv,
       long long sA1, long long sA2,
       long long sB1, long long sB2,
       long long sC1, long long sC2)
{
    constexpr int TX = BN / TN;
    constexpr int TY = BM / TM;
    constexpr int NT = TX * TY;

    const int tid = threadIdx.x;
    const int tx  = tid % TX;
    const int ty  = tid / TX;
    const int n0  = blockIdx.x * BN;
    const int m0  = blockIdx.y * BM;

    if (causal == 1 && n0 > m0 + BM - 1) return;

    {
        const int z  = blockIdx.z;
        const int zb = z / zdiv, zh = z % zdiv;
        A  += zb * sA1 + zh * sA2;
        Bp += zb * sB1 + zh * sB2;
        C  += zb * sC1 + zh * sC2;
        if (EPI == 2) R += zb * sC1 + zh * sC2;
    }

    const int Keff = (causal == 2) ? min(K, m0 + BM) : K;

    __shared__ float As[BK][BM];
    __shared__ float Bs[BK][BN];

    float acc[TM][TN];
    #pragma unroll
    for (int i = 0; i < TM; i++)
        #pragma unroll
        for (int j = 0; j < TN; j++) acc[i][j] = 0.f;

    for (int k0 = 0; k0 < Keff; k0 += BK) {
        for (int t = tid; t < BM * (BK / 4); t += NT) {
            int m  = t / (BK / 4);
            int kq = (t % (BK / 4)) * 4;
            float4 v = make_float4(0.f, 0.f, 0.f, 0.f);
            if (m0 + m < M)
                v = *reinterpret_cast<const float4*>(&A[(long long)(m0 + m) * lda + k0 + kq]);
            As[kq + 0][m] = v.x; As[kq + 1][m] = v.y;
            As[kq + 2][m] = v.z; As[kq + 3][m] = v.w;
        }
        if (!TRANSB) {
            for (int t = tid; t < BK * (BN / 4); t += NT) {
                int kk = t / (BN / 4);
                int nq = (t % (BN / 4)) * 4;
                int n  = n0 + nq;
                float4 v = make_float4(0.f, 0.f, 0.f, 0.f);
                if (n + 3 < N) {
                    v = *reinterpret_cast<const float4*>(&Bp[(long long)(k0 + kk) * ldb + n]);
                } else {
                    if (n + 0 < N) v.x = Bp[(long long)(k0 + kk) * ldb + n + 0];
                    if (n + 1 < N) v.y = Bp[(long long)(k0 + kk) * ldb + n + 1];
                    if (n + 2 < N) v.z = Bp[(long long)(k0 + kk) * ldb + n + 2];
                }
                *reinterpret_cast<float4*>(&Bs[kk][nq]) = v;
            }
        } else {
            for (int t = tid; t < BN * (BK / 4); t += NT) {
                int n  = t / (BK / 4);
                int kq = (t % (BK / 4)) * 4;
                float4 v = make_float4(0.f, 0.f, 0.f, 0.f);
                if (n0 + n < N)
                    v = *reinterpret_cast<const float4*>(&Bp[(long long)(n0 + n) * ldb + k0 + kq]);
                Bs[kq + 0][n] = v.x; Bs[kq + 1][n] = v.y;
                Bs[kq + 2][n] = v.z; Bs[kq + 3][n] = v.w;
            }
        }
        __syncthreads();

        #pragma unroll
        for (int kk = 0; kk < BK; kk++) {
            float a[TM], b[TN];
            #pragma unroll
            for (int i = 0; i < TM; i += 4)
                *reinterpret_cast<float4*>(&a[i]) =
                    *reinterpret_cast<const float4*>(&As[kk][ty * TM + i]);
            #pragma unroll
            for (int j = 0; j < TN; j += 4)
                *reinterpret_cast<float4*>(&b[j]) =
                    *reinterpret_cast<const float4*>(&Bs[kk][tx * TN + j]);
            #pragma unroll
            for (int i = 0; i < TM; i++)
                #pragma unroll
                for (int j = 0; j < TN; j++)
                    acc[i][j] = fmaf(a[i], b[j], acc[i][j]);
        }
        __syncthreads();
    }

    #pragma unroll
    for (int i = 0; i < TM; i++) {
        const int m = m0 + ty * TM + i;
        if (m >= M) continue;
        #pragma unroll
        for (int j = 0; j < TN; j++) {
            const int n = n0 + tx * TN + j;
            if (n >= N) continue;
            float v = acc[i][j] * alpha;
            if (bias) v += bias[n];
            if (EPI == 1) v = gelu_exact(v);
            if (EPI == 2) v += R[(long long)m * ldc + n];
            C[(long long)m * ldc + n] = v;
        }
    }
}

// ---------------------------------------------------------------------------
// LM head: C[M,N] = A[M,K] @ Bm[N,K]^T   via tf32 mma.sync (m16n8k8)
//   Block 128x128x32, 256 threads (8 warps, 2x4), warp tile 64x32.
//   Smem [k][m]/[k][n] padded to stride 136 -> conflict-free fragment loads.
// ---------------------------------------------------------------------------
__global__ void __launch_bounds__(256)
lmhead_tf32_k(const float* __restrict__ A,   // [M,K] row-major
              const float* __restrict__ Bm,  // [N,K] row-major
              float* __restrict__ C,         // [M,N]
              int M, int N, int K)
{
    constexpr int BM = 128, BN = 128, BK = 32, PAD = 8;   // stride 136

    __shared__ float As[BK][BM + PAD];
    __shared__ float Bs[BK][BN + PAD];

    const int tid  = threadIdx.x;
    const int lane = tid & 31;
    const int wid  = tid >> 5;
    const int wm   = wid >> 2;          // 0..1
    const int wn   = wid & 3;           // 0..3
    const int grp  = lane >> 2;         // 0..7
    const int tig  = lane & 3;          // 0..3

    const int m0 = blockIdx.y * BM;
    const int n0 = blockIdx.x * BN;

    // loader mapping: warp = 16 consecutive rows, lanes sweep k (coalesced)
    const int lk = tid & 31;            // k within tile
    const int lg = tid >> 5;            // row-group, rows lg*16 .. lg*16+15

    float acc[4][4][4];
    #pragma unroll
    for (int mi = 0; mi < 4; mi++)
        #pragma unroll
        for (int nj = 0; nj < 4; nj++)
            #pragma unroll
            for (int c = 0; c < 4; c++) acc[mi][nj][c] = 0.f;

    for (int kb = 0; kb < K; kb += BK) {
        // ---- A tile: rows m0+lg*16+j, col kb+lk; store As[k][m] ----
        #pragma unroll
        for (int jc = 0; jc < 4; jc++) {
            const int mb = m0 + lg * 16 + jc * 4;
            float4 v;
            v.x = f2tf32(A[(long long)(mb + 0) * K + kb + lk]);
            v.y = f2tf32(A[(long long)(mb + 1) * K + kb + lk]);
            v.z = f2tf32(A[(long long)(mb + 2) * K + kb + lk]);
            v.w = f2tf32(A[(long long)(mb + 3) * K + kb + lk]);
            *reinterpret_cast<float4*>(&As[lk][lg * 16 + jc * 4]) = v;
        }
        // ---- B tile: rows n0+lg*16+j (guarded), col kb+lk; store Bs[k][n] ----
        #pragma unroll
        for (int jc = 0; jc < 4; jc++) {
            const int nb = n0 + lg * 16 + jc * 4;
            float4 v = make_float4(0.f, 0.f, 0.f, 0.f);
            if (nb + 0 < N) v.x = f2tf32(Bm[(long long)(nb + 0) * K + kb + lk]);
            if (nb + 1 < N) v.y = f2tf32(Bm[(long long)(nb + 1) * K + kb + lk]);
            if (nb + 2 < N) v.z = f2tf32(Bm[(long long)(nb + 2) * K + kb + lk]);
            if (nb + 3 < N) v.w = f2tf32(Bm[(long long)(nb + 3) * K + kb + lk]);
            *reinterpret_cast<float4*>(&Bs[lk][lg * 16 + jc * 4]) = v;
        }
        __syncthreads();

        #pragma unroll
        for (int kk = 0; kk < BK / 8; kk++) {
            const int k8 = kk * 8;
            uint32_t af[4][4], bf[4][2];
            #pragma unroll
            for (int mi = 0; mi < 4; mi++) {
                const int r = wm * 64 + mi * 16 + grp;
                af[mi][0] = __float_as_uint(As[k8 + tig    ][r    ]);
                af[mi][1] = __float_as_uint(As[k8 + tig    ][r + 8]);
                af[mi][2] = __float_as_uint(As[k8 + tig + 4][r    ]);
                af[mi][3] = __float_as_uint(As[k8 + tig + 4][r + 8]);
            }
            #pragma unroll
            for (int nj = 0; nj < 4; nj++) {
                const int c = wn * 32 + nj * 8 + grp;
                bf[nj][0] = __float_as_uint(Bs[k8 + tig    ][c]);
                bf[nj][1] = __float_as_uint(Bs[k8 + tig + 4][c]);
            }
            #pragma unroll
            for (int mi = 0; mi < 4; mi++)
                #pragma unroll
                for (int nj = 0; nj < 4; nj++) {
                    asm volatile(
                        "mma.sync.aligned.m16n8k8.row.col.f32.tf32.tf32.f32 "
                        "{%0,%1,%2,%3}, {%4,%5,%6,%7}, {%8,%9}, {%0,%1,%2,%3};\n"
                        : "+f"(acc[mi][nj][0]), "+f"(acc[mi][nj][1]),
                          "+f"(acc[mi][nj][2]), "+f"(acc[mi][nj][3])
                        : "r"(af[mi][0]), "r"(af[mi][1]), "r"(af[mi][2]), "r"(af[mi][3]),
                          "r"(bf[nj][0]), "r"(bf[nj][1]));
                }
        }
        __syncthreads();
    }

    // ---- epilogue ----
    #pragma unroll
    for (int mi = 0; mi < 4; mi++) {
        const int r = m0 + wm * 64 + mi * 16 + grp;
        #pragma unroll
        for (int nj = 0; nj < 4; nj++) {
            const int c = n0 + wn * 32 + nj * 8 + tig * 2;
            if (c < N)     C[(long long)r * N + c]           = acc[mi][nj][0];
            if (c + 1 < N) C[(long long)r * N + c + 1]       = acc[mi][nj][1];
            if (c < N)     C[(long long)(r + 8) * N + c]     = acc[mi][nj][2];
            if (c + 1 < N) C[(long long)(r + 8) * N + c + 1] = acc[mi][nj][3];
        }
    }
}

// ---------------------------------------------------------------------------
// Embedding: h[b,s,:] = tok_emb[id] + pos_emb[s]
// ---------------------------------------------------------------------------
__global__ void embed_k(const int* __restrict__ ids, const float* __restrict__ tok,
                        const float* __restrict__ pos, float* __restrict__ h)
{
    int idx = blockIdx.x * 256 + threadIdx.x;
    if (idx >= BS * D) return;
    int d  = idx & (D - 1);
    int bs = idx >> 8;              // D == 256
    int s  = bs & (S - 1);
    h[idx] = tok[(long long)ids[bs] * D + d] + pos[s * D + d];
}

// ---------------------------------------------------------------------------
// LayerNorm: one block per row, D=256 threads, eps=1e-5, biased variance
// ---------------------------------------------------------------------------
__global__ void layernorm_k(const float* __restrict__ x, float* __restrict__ y,
                            const float* __restrict__ sc, const float* __restrict__ bi)
{
    const int row = blockIdx.x;
    const int tid = threadIdx.x;        // blockDim = D = 256
    const float v = x[(long long)row * D + tid];

    float s1 = v, s2 = v * v;
    #pragma unroll
    for (int o = 16; o > 0; o >>= 1) {
        s1 += __shfl_xor_sync(0xffffffffu, s1, o);
        s2 += __shfl_xor_sync(0xffffffffu, s2, o);
    }
    __shared__ float a1[8], a2[8];
    if ((tid & 31) == 0) { a1[tid >> 5] = s1; a2[tid >> 5] = s2; }
    __syncthreads();
    if (tid < 32) {
        float t1 = (tid < 8) ? a1[tid] : 0.f;
        float t2 = (tid < 8) ? a2[tid] : 0.f;
        #pragma unroll
        for (int o = 4; o > 0; o >>= 1) {
            t1 += __shfl_xor_sync(0xffffffffu, t1, o);
            t2 += __shfl_xor_sync(0xffffffffu, t2, o);
        }
        if (tid == 0) { a1[0] = t1; a2[0] = t2; }
    }
    __syncthreads();
    const float mean = a1[0] * (1.f / D);
    const float var  = a2[0] * (1.f / D) - mean * mean;
    const float r    = rsqrtf(var + 1e-5f);
    y[(long long)row * D + tid] = (v - mean) * r * sc[tid] + bi[tid];
}

// ---------------------------------------------------------------------------
// Causal softmax over score rows; writes exact 0 for masked positions.
// ---------------------------------------------------------------------------
__global__ void softmax_causal_k(float* __restrict__ att)
{
    const int  row   = blockIdx.x;
    const int  q     = row & (S - 1);
    const int  valid = q + 1;
    const int  tid   = threadIdx.x;     // 256
    float* p = att + (long long)row * S;

    float x[S / 256];
    int   cnt = 0;
    float mx  = -INFINITY;
    for (int c = tid; c < valid; c += 256) { x[cnt] = p[c]; mx = fmaxf(mx, x[cnt]); cnt++; }

    __shared__ float sh[8];
    #pragma unroll
    for (int o = 16; o > 0; o >>= 1) mx = fmaxf(mx, __shfl_xor_sync(0xffffffffu, mx, o));
    if ((tid & 31) == 0) sh[tid >> 5] = mx;
    __syncthreads();
    if (tid < 32) {
        float t = (tid < 8) ? sh[tid] : -INFINITY;
        #pragma unroll
        for (int o = 4; o > 0; o >>= 1) t = fmaxf(t, __shfl_xor_sync(0xffffffffu, t, o));
        if (tid == 0) sh[0] = t;
    }
    __syncthreads();
    mx = sh[0];
    __syncthreads();

    float sum = 0.f;
    for (int i = 0; i < cnt; i++) { x[i] = expf(x[i] - mx); sum += x[i]; }
    #pragma unroll
    for (int o = 16; o > 0; o >>= 1) sum += __shfl_xor_sync(0xffffffffu, sum, o);
    if ((tid & 31) == 0) sh[tid >> 5] = sum;
    __syncthreads();
    if (tid < 32) {
        float t = (tid < 8) ? sh[tid] : 0.f;
        #pragma unroll
        for (int o = 4; o > 0; o >>= 1) t += __shfl_xor_sync(0xffffffffu, t, o);
        if (tid == 0) sh[0] = t;
    }
    __syncthreads();
    const float inv = 1.0f / sh[0];

    cnt = 0;
    for (int c = tid; c < valid; c += 256) p[c] = x[cnt++] * inv;
    for (int c = tid; c < S; c += 256) if (c >= valid) p[c] = 0.f;
}

// ---------------------------------------------------------------------------
// Driver -- all launches on the default stream; graph-capturable, no allocs.
// ---------------------------------------------------------------------------
extern "C" void kernel_launch(void* const* d_in, const int* in_sizes, int n_in,
                              void* d_out, int out_size)
{
    (void)in_sizes; (void)n_in; (void)out_size;

    const int*   ids  = (const int*)  d_in[0];
    const float* tok  = (const float*)d_in[1];
    const float* pos  = (const float*)d_in[2];
    const float* Wq   = (const float*)d_in[3];
    const float* bq   = (const float*)d_in[4];
    const float* Wk   = (const float*)d_in[5];
    const float* bk   = (const float*)d_in[6];
    const float* Wv   = (const float*)d_in[7];
    const float* bv   = (const float*)d_in[8];
    const float* Wo   = (const float*)d_in[9];
    const float* bo   = (const float*)d_in[10];
    const float* ln1s = (const float*)d_in[11];
    const float* ln1b = (const float*)d_in[12];
    const float* ln2s = (const float*)d_in[13];
    const float* ln2b = (const float*)d_in[14];
    const float* W1   = (const float*)d_in[15];
    const float* b1   = (const float*)d_in[16];
    const float* W2   = (const float*)d_in[17];
    const float* b2   = (const float*)d_in[18];
    const float* lnfs = (const float*)d_in[19];
    const float* lnfb = (const float*)d_in[20];
    float* out = (float*)d_out;

    float *gh, *gn, *gq, *gk, *gv, *go, *gf, *ga;
    cudaGetSymbolAddress((void**)&gh, g_h);
    cudaGetSymbolAddress((void**)&gn, g_n);
    cudaGetSymbolAddress((void**)&gq, g_q);
    cudaGetSymbolAddress((void**)&gk, g_k);
    cudaGetSymbolAddress((void**)&gv, g_v);
    cudaGetSymbolAddress((void**)&go, g_o);
    cudaGetSymbolAddress((void**)&gf, g_f1);
    cudaGetSymbolAddress((void**)&ga, g_att);

    const long long SD  = (long long)S * D;
    const long long SS  = (long long)S * S;
    const long long HSS = (long long)H * S * S;

    embed_k<<<(BS * D + 255) / 256, 256>>>(ids, tok, pos, gh);

    for (int l = 0; l < L; l++) {
        const float* wq = Wq + (long long)l * D * D;
        const float* wk = Wk + (long long)l * D * D;
        const float* wv = Wv + (long long)l * D * D;
        const float* wo = Wo + (long long)l * D * D;
        const float* w1 = W1 + (long long)l * D * DF;
        const float* w2 = W2 + (long long)l * DF * D;

        // LN1
        layernorm_k<<<BS, D>>>(gh, gn, ln1s + l * D, ln1b + l * D);

        // Q, K, V projections: 64x64 tiles -> 256 blocks (better occupancy)
        dim3 gP(D / 64, BS / 64, 1);
        gemm_k<64,64,8,4,4,false,0><<<gP, 256>>>(gn, D, wq, D, gq, D, bq + l * D, nullptr,
            BS, D, D, 1.f, 0, 1, 0,0,0,0,0,0);
        gemm_k<64,64,8,4,4,false,0><<<gP, 256>>>(gn, D, wk, D, gk, D, bk + l * D, nullptr,
            BS, D, D, 1.f, 0, 1, 0,0,0,0,0,0);
        gemm_k<64,64,8,4,4,false,0><<<gP, 256>>>(gn, D, wv, D, gv, D, bv + l * D, nullptr,
            BS, D, D, 1.f, 0, 1, 0,0,0,0,0,0);

        // Scores = scale * Q @ K^T  (batched over b,h; causal block-skip)
        dim3 gS(S / 128, S / 128, B * H);
        gemm_k<128,128,8,8,8,true,0><<<gS, 256>>>(gq, D, gk, D, ga, S, nullptr, nullptr,
            S, S, HD, 0.125f /* HD^-0.5 */, 1,
            H, SD, HD, SD, HD, HSS, SS);

        // Causal softmax (writes exact zeros for masked cols)
        softmax_causal_k<<<B * H * S, 256>>>(ga);

        // O = attn @ V  (batched; K limited to causal extent per block-row)
        dim3 gA(HD / 64, S / 64, B * H);
        gemm_k<64,64,8,4,4,false,0><<<gA, 256>>>(ga, S, gv, D, go, D, nullptr, nullptr,
            S, HD, S, 1.f, 2,
            H, HSS, SS, SD, HD, SD, HD);

        // h = h + O @ Wo + bo
        gemm_k<64,64,8,4,4,false,2><<<gP, 256>>>(go, D, wo, D, gh, D, bo + l * D, gh,
            BS, D, D, 1.f, 0, 1, 0,0,0,0,0,0);

        // LN2
        layernorm_k<<<BS, D>>>(gh, gn, ln2s + l * D, ln2b + l * D);

        // FFN1: gelu(n @ W1 + b1)   (4096 x 1024)
        dim3 gF1(DF / 128, BS / 128, 1);
        gemm_k<128,128,8,8,8,false,1><<<gF1, 256>>>(gn, D, w1, DF, gf, DF, b1 + l * DF, nullptr,
            BS, DF, D, 1.f, 0, 1, 0,0,0,0,0,0);

        // h = h + f @ W2 + b2  (64x64 tiles -> 256 blocks)
        dim3 gF2(D / 64, BS / 64, 1);
        gemm_k<64,64,8,4,4,false,2><<<gF2, 256>>>(gf, DF, w2, D, gh, D, b2 + l * D, gh,
            BS, D, DF, 1.f, 0, 1, 0,0,0,0,0,0);
    }

    // Final LN
    layernorm_k<<<BS, D>>>(gh, gn, lnfs, lnfb);

    // LM head: logits = n @ tok_emb^T  via tf32 tensor cores
    dim3 gL((V + 127) / 128, BS / 128, 1);
    lmhead_tf32_k<<<gL, 256>>>(gn, tok, out, BS, V, D);
}

// round 9
// speedup vs baseline: 1.8322x; 1.5033x over previous
#include <cuda_runtime.h>
#include <math.h>
#include <stdint.h>

// ---------------------------------------------------------------------------
// Problem constants (match reference)
// ---------------------------------------------------------------------------
namespace {
constexpr int B  = 2;
constexpr int S  = 2048;
constexpr int D  = 256;
constexpr int H  = 4;
constexpr int HD = 64;
constexpr int L  = 4;
constexpr int V  = 50257;
constexpr int DF = 1024;          // 4*D
constexpr int BS = B * S;         // 4096 tokens
}

// ---------------------------------------------------------------------------
// Scratch (static device globals -- no allocations allowed)
// ---------------------------------------------------------------------------
__device__ float g_h [BS * D];
__device__ float g_n [BS * D];
__device__ float g_q [BS * D];
__device__ float g_k [BS * D];
__device__ float g_v [BS * D];
__device__ float g_o [BS * D];
__device__ float g_f1[BS * DF];
__device__ float g_att[(long long)B * H * S * S];   // 134 MB

#define DEV_INLINE __device__ __forceinline__

DEV_INLINE float gelu_exact(float x) {
    return 0.5f * x * (1.0f + erff(x * 0.70710678118654752f));
}

DEV_INLINE float f2tf32(float x) {   // round-to-nearest tf32, kept in fp32 bits
    uint32_t u;
    asm("cvt.rna.tf32.f32 %0, %1;" : "=r"(u) : "f"(x));
    return __uint_as_float(u);
}

// ---------------------------------------------------------------------------
// Generic tf32 tensor-core GEMM (mma.sync.m16n8k8), 256 threads = 8 warps.
//   C[m][n] = alpha * sum_k A[m][k]*B[k][n]  (+bias, gelu, +resid)
//   TRANSB: B given as Bm[N,K] row-major (NT form). Else Bp[K,N] (NN form).
//   Warp grid WM x WN (WM*WN == 8); warp tile (BM/WM) x (BN/WN).
//   EPI: 0 = optional bias; 1 = gelu(acc+bias); 2 = resid + acc + bias
//   causal: 0 none; 1 skip blocks fully above diagonal (scores);
//           2 limit K to m0+BM (attn @ V; masked attn entries are exact 0)
//   Requires: M % BM == 0, K % 32 == 0; NN path also N % BN == 0.
//   N-guards active in TRANSB loader + epilogue (LM head tail).
// ---------------------------------------------------------------------------
template<int BM, int BN, int WM, int WN, bool TRANSB, int EPI>
__global__ void __launch_bounds__(256)
tgemm_k(const float* __restrict__ A,  int lda,
        const float* __restrict__ Bp, int ldb,
        float* __restrict__ C,        int ldc,
        const float* __restrict__ bias,
        const float* __restrict__ R,
        int M, int N, int K, float alpha, int causal,
        int zdiv,
        long long sA1, long long sA2,
        long long sB1, long long sB2,
        long long sC1, long long sC2)
{
    constexpr int BK  = 32;
    constexpr int PAD = 8;                    // row stride BM+8 / BN+8
    constexpr int MF  = BM / (WM * 16);       // m16 frags per warp
    constexpr int NF  = BN / (WN * 8);        // n8 frags per warp

    __shared__ float As[BK][BM + PAD];
    __shared__ float Bs[BK][BN + PAD];

    const int tid  = threadIdx.x;
    const int lane = tid & 31;
    const int wid  = tid >> 5;
    const int wm   = wid / WN;
    const int wn   = wid % WN;
    const int grp  = lane >> 2;               // 0..7
    const int tig  = lane & 3;                // 0..3

    const int n0 = blockIdx.x * BN;
    const int m0 = blockIdx.y * BM;

    if (causal == 1 && n0 > m0 + BM - 1) return;

    {
        const int z  = blockIdx.z;
        const int zb = z / zdiv, zh = z % zdiv;
        A  += zb * sA1 + zh * sA2;
        Bp += zb * sB1 + zh * sB2;
        C  += zb * sC1 + zh * sC2;
        if (EPI == 2) R += zb * sC1 + zh * sC2;
    }

    const int Keff = (causal == 2) ? min(K, m0 + BM) : K;

    // loader mapping: lane sweeps k (coalesced), warp owns BM/8 rows
    const int lk = lane;
    const int lg = wid;

    float acc[MF][NF][4];
    #pragma unroll
    for (int mi = 0; mi < MF; mi++)
        #pragma unroll
        for (int nj = 0; nj < NF; nj++)
            #pragma unroll
            for (int c = 0; c < 4; c++) acc[mi][nj][c] = 0.f;

    for (int kb = 0; kb < Keff; kb += BK) {
        // ---- A tile (BM x 32) -> As[k][m], rows always in-bounds ----
        #pragma unroll
        for (int jc = 0; jc < BM / 32; jc++) {
            const int mb = m0 + lg * (BM / 8) + jc * 4;
            float4 v;
            v.x = f2tf32(A[(long long)(mb + 0) * lda + kb + lk]);
            v.y = f2tf32(A[(long long)(mb + 1) * lda + kb + lk]);
            v.z = f2tf32(A[(long long)(mb + 2) * lda + kb + lk]);
            v.w = f2tf32(A[(long long)(mb + 3) * lda + kb + lk]);
            *reinterpret_cast<float4*>(&As[lk][lg * (BM / 8) + jc * 4]) = v;
        }
        // ---- B tile -> Bs[k][n] ----
        if (TRANSB) {
            #pragma unroll
            for (int jc = 0; jc < BN / 32; jc++) {
                const int nb = n0 + lg * (BN / 8) + jc * 4;
                float4 v = make_float4(0.f, 0.f, 0.f, 0.f);
                if (nb + 0 < N) v.x = f2tf32(Bp[(long long)(nb + 0) * ldb + kb + lk]);
                if (nb + 1 < N) v.y = f2tf32(Bp[(long long)(nb + 1) * ldb + kb + lk]);
                if (nb + 2 < N) v.z = f2tf32(Bp[(long long)(nb + 2) * ldb + kb + lk]);
                if (nb + 3 < N) v.w = f2tf32(Bp[(long long)(nb + 3) * ldb + kb + lk]);
                *reinterpret_cast<float4*>(&Bs[lk][lg * (BN / 8) + jc * 4]) = v;
            }
        } else {
            #pragma unroll
            for (int t = tid; t < BK * (BN / 4); t += 256) {
                const int kk = t / (BN / 4);
                const int nq = (t % (BN / 4)) * 4;
                float4 v = *reinterpret_cast<const float4*>(
                    &Bp[(long long)(kb + kk) * ldb + n0 + nq]);
                v.x = f2tf32(v.x); v.y = f2tf32(v.y);
                v.z = f2tf32(v.z); v.w = f2tf32(v.w);
                *reinterpret_cast<float4*>(&Bs[kk][nq]) = v;
            }
        }
        __syncthreads();

        #pragma unroll
        for (int kk8 = 0; kk8 < BK / 8; kk8++) {
            const int k8 = kk8 * 8;
            uint32_t af[MF][4], bf[NF][2];
            #pragma unroll
            for (int mi = 0; mi < MF; mi++) {
                const int r = wm * (MF * 16) + mi * 16 + grp;
                af[mi][0] = __float_as_uint(As[k8 + tig    ][r    ]);
                af[mi][1] = __float_as_uint(As[k8 + tig    ][r + 8]);
                af[mi][2] = __float_as_uint(As[k8 + tig + 4][r    ]);
                af[mi][3] = __float_as_uint(As[k8 + tig + 4][r + 8]);
            }
            #pragma unroll
            for (int nj = 0; nj < NF; nj++) {
                const int c = wn * (NF * 8) + nj * 8 + grp;
                bf[nj][0] = __float_as_uint(Bs[k8 + tig    ][c]);
                bf[nj][1] = __float_as_uint(Bs[k8 + tig + 4][c]);
            }
            #pragma unroll
            for (int mi = 0; mi < MF; mi++)
                #pragma unroll
                for (int nj = 0; nj < NF; nj++) {
                    asm volatile(
                        "mma.sync.aligned.m16n8k8.row.col.f32.tf32.tf32.f32 "
                        "{%0,%1,%2,%3}, {%4,%5,%6,%7}, {%8,%9}, {%0,%1,%2,%3};\n"
                        : "+f"(acc[mi][nj][0]), "+f"(acc[mi][nj][1]),
                          "+f"(acc[mi][nj][2]), "+f"(acc[mi][nj][3])
                        : "r"(af[mi][0]), "r"(af[mi][1]), "r"(af[mi][2]), "r"(af[mi][3]),
                          "r"(bf[nj][0]), "r"(bf[nj][1]));
                }
        }
        __syncthreads();
    }

    // ---- epilogue ----
    #pragma unroll
    for (int mi = 0; mi < MF; mi++) {
        const int r = m0 + wm * (MF * 16) + mi * 16 + grp;
        #pragma unroll
        for (int nj = 0; nj < NF; nj++) {
            const int c = n0 + wn * (NF * 8) + nj * 8 + tig * 2;
            float v0 = acc[mi][nj][0] * alpha;
            float v1 = acc[mi][nj][1] * alpha;
            float v2 = acc[mi][nj][2] * alpha;
            float v3 = acc[mi][nj][3] * alpha;
            if (bias) {
                const float b0 = (c     < N) ? bias[c]     : 0.f;
                const float b1 = (c + 1 < N) ? bias[c + 1] : 0.f;
                v0 += b0; v1 += b1; v2 += b0; v3 += b1;
            }
            if (EPI == 1) {
                v0 = gelu_exact(v0); v1 = gelu_exact(v1);
                v2 = gelu_exact(v2); v3 = gelu_exact(v3);
            }
            if (EPI == 2) {
                if (c     < N) { v0 += R[(long long)r * ldc + c];
                                 v2 += R[(long long)(r + 8) * ldc + c]; }
                if (c + 1 < N) { v1 += R[(long long)r * ldc + c + 1];
                                 v3 += R[(long long)(r + 8) * ldc + c + 1]; }
            }
            if (c     < N) { C[(long long)r * ldc + c]           = v0;
                             C[(long long)(r + 8) * ldc + c]     = v2; }
            if (c + 1 < N) { C[(long long)r * ldc + c + 1]       = v1;
                             C[(long long)(r + 8) * ldc + c + 1] = v3; }
        }
    }
}

// ---------------------------------------------------------------------------
// Embedding: h[b,s,:] = tok_emb[id] + pos_emb[s]
// ---------------------------------------------------------------------------
__global__ void embed_k(const int* __restrict__ ids, const float* __restrict__ tok,
                        const float* __restrict__ pos, float* __restrict__ h)
{
    int idx = blockIdx.x * 256 + threadIdx.x;
    if (idx >= BS * D) return;
    int d  = idx & (D - 1);
    int bs = idx >> 8;              // D == 256
    int s  = bs & (S - 1);
    h[idx] = tok[(long long)ids[bs] * D + d] + pos[s * D + d];
}

// ---------------------------------------------------------------------------
// LayerNorm: one block per row, D=256 threads, eps=1e-5, biased variance
// ---------------------------------------------------------------------------
__global__ void layernorm_k(const float* __restrict__ x, float* __restrict__ y,
                            const float* __restrict__ sc, const float* __restrict__ bi)
{
    const int row = blockIdx.x;
    const int tid = threadIdx.x;        // blockDim = D = 256
    const float v = x[(long long)row * D + tid];

    float s1 = v, s2 = v * v;
    #pragma unroll
    for (int o = 16; o > 0; o >>= 1) {
        s1 += __shfl_xor_sync(0xffffffffu, s1, o);
        s2 += __shfl_xor_sync(0xffffffffu, s2, o);
    }
    __shared__ float a1[8], a2[8];
    if ((tid & 31) == 0) { a1[tid >> 5] = s1; a2[tid >> 5] = s2; }
    __syncthreads();
    if (tid < 32) {
        float t1 = (tid < 8) ? a1[tid] : 0.f;
        float t2 = (tid < 8) ? a2[tid] : 0.f;
        #pragma unroll
        for (int o = 4; o > 0; o >>= 1) {
            t1 += __shfl_xor_sync(0xffffffffu, t1, o);
            t2 += __shfl_xor_sync(0xffffffffu, t2, o);
        }
        if (tid == 0) { a1[0] = t1; a2[0] = t2; }
    }
    __syncthreads();
    const float mean = a1[0] * (1.f / D);
    const float var  = a2[0] * (1.f / D) - mean * mean;
    const float r    = rsqrtf(var + 1e-5f);
    y[(long long)row * D + tid] = (v - mean) * r * sc[tid] + bi[tid];
}

// ---------------------------------------------------------------------------
// Causal softmax over score rows. Zero-fills only up to the next multiple of
// 64 past `valid` (the attn@V GEMM's causal K-limit granularity) -- columns
// beyond that are never read.
// ---------------------------------------------------------------------------
__global__ void softmax_causal_k(float* __restrict__ att)
{
    const int  row   = blockIdx.x;
    const int  q     = row & (S - 1);
    const int  valid = q + 1;
    const int  tid   = threadIdx.x;     // 256
    float* p = att + (long long)row * S;

    float x[S / 256];
    int   cnt = 0;
    float mx  = -INFINITY;
    for (int c = tid; c < valid; c += 256) { x[cnt] = p[c]; mx = fmaxf(mx, x[cnt]); cnt++; }

    __shared__ float sh[8];
    #pragma unroll
    for (int o = 16; o > 0; o >>= 1) mx = fmaxf(mx, __shfl_xor_sync(0xffffffffu, mx, o));
    if ((tid & 31) == 0) sh[tid >> 5] = mx;
    __syncthreads();
    if (tid < 32) {
        float t = (tid < 8) ? sh[tid] : -INFINITY;
        #pragma unroll
        for (int o = 4; o > 0; o >>= 1) t = fmaxf(t, __shfl_xor_sync(0xffffffffu, t, o));
        if (tid == 0) sh[0] = t;
    }
    __syncthreads();
    mx = sh[0];
    __syncthreads();

    float sum = 0.f;
    for (int i = 0; i < cnt; i++) { x[i] = expf(x[i] - mx); sum += x[i]; }
    #pragma unroll
    for (int o = 16; o > 0; o >>= 1) sum += __shfl_xor_sync(0xffffffffu, sum, o);
    if ((tid & 31) == 0) sh[tid >> 5] = sum;
    __syncthreads();
    if (tid < 32) {
        float t = (tid < 8) ? sh[tid] : 0.f;
        #pragma unroll
        for (int o = 4; o > 0; o >>= 1) t += __shfl_xor_sync(0xffffffffu, t, o);
        if (tid == 0) sh[0] = t;
    }
    __syncthreads();
    const float inv = 1.0f / sh[0];

    cnt = 0;
    for (int c = tid; c < valid; c += 256) p[c] = x[cnt++] * inv;

    // zero-fill [valid, round_up(valid, 64)) -- the only masked cols attn@V reads
    const int zlim = ((q >> 6) + 1) << 6;
    for (int c = valid + tid; c < zlim; c += 256) p[c] = 0.f;
}

// ---------------------------------------------------------------------------
// Driver -- all launches on the default stream; graph-capturable, no allocs.
// ---------------------------------------------------------------------------
extern "C" void kernel_launch(void* const* d_in, const int* in_sizes, int n_in,
                              void* d_out, int out_size)
{
    (void)in_sizes; (void)n_in; (void)out_size;

    const int*   ids  = (const int*)  d_in[0];
    const float* tok  = (const float*)d_in[1];
    const float* pos  = (const float*)d_in[2];
    const float* Wq   = (const float*)d_in[3];
    const float* bq   = (const float*)d_in[4];
    const float* Wk   = (const float*)d_in[5];
    const float* bk   = (const float*)d_in[6];
    const float* Wv   = (const float*)d_in[7];
    const float* bv   = (const float*)d_in[8];
    const float* Wo   = (const float*)d_in[9];
    const float* bo   = (const float*)d_in[10];
    const float* ln1s = (const float*)d_in[11];
    const float* ln1b = (const float*)d_in[12];
    const float* ln2s = (const float*)d_in[13];
    const float* ln2b = (const float*)d_in[14];
    const float* W1   = (const float*)d_in[15];
    const float* b1   = (const float*)d_in[16];
    const float* W2   = (const float*)d_in[17];
    const float* b2   = (const float*)d_in[18];
    const float* lnfs = (const float*)d_in[19];
    const float* lnfb = (const float*)d_in[20];
    float* out = (float*)d_out;

    float *gh, *gn, *gq, *gk, *gv, *go, *gf, *ga;
    cudaGetSymbolAddress((void**)&gh, g_h);
    cudaGetSymbolAddress((void**)&gn, g_n);
    cudaGetSymbolAddress((void**)&gq, g_q);
    cudaGetSymbolAddress((void**)&gk, g_k);
    cudaGetSymbolAddress((void**)&gv, g_v);
    cudaGetSymbolAddress((void**)&go, g_o);
    cudaGetSymbolAddress((void**)&gf, g_f1);
    cudaGetSymbolAddress((void**)&ga, g_att);

    const long long SD  = (long long)S * D;
    const long long SS  = (long long)S * S;
    const long long HSS = (long long)H * S * S;

    embed_k<<<(BS * D + 255) / 256, 256>>>(ids, tok, pos, gh);

    for (int l = 0; l < L; l++) {
        const float* wq = Wq + (long long)l * D * D;
        const float* wk = Wk + (long long)l * D * D;
        const float* wv = Wv + (long long)l * D * D;
        const float* wo = Wo + (long long)l * D * D;
        const float* w1 = W1 + (long long)l * D * DF;
        const float* w2 = W2 + (long long)l * DF * D;

        // LN1
        layernorm_k<<<BS, D>>>(gh, gn, ln1s + l * D, ln1b + l * D);

        // Q, K, V projections: (4096 x 256 x 256), tf32, 64x64 tiles
        dim3 gP(D / 64, BS / 64, 1);
        tgemm_k<64,64,2,4,false,0><<<gP, 256>>>(gn, D, wq, D, gq, D, bq + l * D, nullptr,
            BS, D, D, 1.f, 0, 1, 0,0,0,0,0,0);
        tgemm_k<64,64,2,4,false,0><<<gP, 256>>>(gn, D, wk, D, gk, D, bk + l * D, nullptr,
            BS, D, D, 1.f, 0, 1, 0,0,0,0,0,0);
        tgemm_k<64,64,2,4,false,0><<<gP, 256>>>(gn, D, wv, D, gv, D, bv + l * D, nullptr,
            BS, D, D, 1.f, 0, 1, 0,0,0,0,0,0);

        // Scores = scale * Q @ K^T  (batched over b,h; causal block-skip; NT)
        dim3 gS(S / 128, S / 128, B * H);
        tgemm_k<128,128,2,4,true,0><<<gS, 256>>>(gq, D, gk, D, ga, S, nullptr, nullptr,
            S, S, HD, 0.125f /* HD^-0.5 */, 1,
            H, SD, HD, SD, HD, HSS, SS);

        // Causal softmax (zero-fills only the 64-col K-limit fringe)
        softmax_causal_k<<<B * H * S, 256>>>(ga);

        // O = attn @ V  (batched; K limited to causal extent per block-row)
        dim3 gA(HD / 64, S / 64, B * H);
        tgemm_k<64,64,2,4,false,0><<<gA, 256>>>(ga, S, gv, D, go, D, nullptr, nullptr,
            S, HD, S, 1.f, 2,
            H, HSS, SS, SD, HD, SD, HD);

        // h = h + O @ Wo + bo
        tgemm_k<64,64,2,4,false,2><<<gP, 256>>>(go, D, wo, D, gh, D, bo + l * D, gh,
            BS, D, D, 1.f, 0, 1, 0,0,0,0,0,0);

        // LN2
        layernorm_k<<<BS, D>>>(gh, gn, ln2s + l * D, ln2b + l * D);

        // FFN1: gelu(n @ W1 + b1)   (4096 x 1024 x 256), 128x128 tiles
        dim3 gF1(DF / 128, BS / 128, 1);
        tgemm_k<128,128,2,4,false,1><<<gF1, 256>>>(gn, D, w1, DF, gf, DF, b1 + l * DF, nullptr,
            BS, DF, D, 1.f, 0, 1, 0,0,0,0,0,0);

        // h = h + f @ W2 + b2   (4096 x 256 x 1024)
        dim3 gF2(D / 64, BS / 64, 1);
        tgemm_k<64,64,2,4,false,2><<<gF2, 256>>>(gf, DF, w2, D, gh, D, b2 + l * D, gh,
            BS, D, DF, 1.f, 0, 1, 0,0,0,0,0,0);
    }

    // Final LN
    layernorm_k<<<BS, D>>>(gh, gn, lnfs, lnfb);

    // LM head: logits = n @ tok_emb^T   (4096 x 50257 x 256, NT, tf32)
    dim3 gL((V + 127) / 128, BS / 128, 1);
    tgemm_k<128,128,2,4,true,0><<<gL, 256>>>(gn, D, tok, D, out, V, nullptr, nullptr,
        BS, V, D, 1.f, 0, 1, 0,0,0,0,0,0);
}